// round 6
// baseline (speedup 1.0000x reference)
#include <cuda_runtime.h>
#include <cuda_bf16.h>

// Problem constants (from reference)
#define N_SAMPLES 65536
#define N_DIMS    128
#define K_NEG     10

constexpr int WARPS_PER_BLOCK = 8;
constexpr int THREADS = WARPS_PER_BLOCK * 32;
constexpr int NBLOCKS = N_SAMPLES / WARPS_PER_BLOCK;   // 8192

// Scratch for deterministic two-stage reduction (no device allocation allowed)
__device__ float g_partials[NBLOCKS];

// Numerically stable log-sigmoid: logsig(x) = min(x,0) - log1p(exp(-|x|))
__device__ __forceinline__ float log_sigmoid(float x) {
    return fminf(x, 0.0f) - log1pf(__expf(-fabsf(x)));
}

__global__ void __launch_bounds__(THREADS)
skipgram_main_kernel(const int* __restrict__ input_idx,
                     const int* __restrict__ output_idx,
                     const int* __restrict__ neg_idx,
                     const float* __restrict__ W_in,
                     const float* __restrict__ W_out)
{
    const int warp = threadIdx.x >> 5;
    const int lane = threadIdx.x & 31;
    const int s = blockIdx.x * WARPS_PER_BLOCK + warp;   // sample id

    const float4* __restrict__ Win4  = reinterpret_cast<const float4*>(W_in);
    const float4* __restrict__ Wout4 = reinterpret_cast<const float4*>(W_out);

    // Indices: uniform broadcast loads for in/out; lanes 0..9 carry neg indices
    const int ii = __ldg(input_idx  + s);
    const int oi = __ldg(output_idx + s);
    const int nlane = (lane < K_NEG) ? lane : 0;
    const int ni = __ldg(neg_idx + (size_t)s * K_NEG + nlane);

    // Broadcast all neg indices up front so the 10 row loads have no
    // serializing dependency -> ptxas can front-batch all LDG.128s (max MLP).
    int nidx[K_NEG];
    #pragma unroll
    for (int k = 0; k < K_NEG; k++)
        nidx[k] = __shfl_sync(0xffffffffu, ni, k);

    // Row slice per lane: 128 dims = 32 lanes x float4 (512B coalesced row)
    const float4 a = __ldg(Win4  + (size_t)ii * 32 + lane);
    const float4 b = __ldg(Wout4 + (size_t)oi * 32 + lane);

    float4 c[K_NEG];
    #pragma unroll
    for (int k = 0; k < K_NEG; k++)
        c[k] = __ldg(Wout4 + (size_t)nidx[k] * 32 + lane);

    float dots[K_NEG + 1];
    dots[0] = a.x * b.x + a.y * b.y + a.z * b.z + a.w * b.w;
    #pragma unroll
    for (int k = 0; k < K_NEG; k++)
        dots[k + 1] = a.x * c[k].x + a.y * c[k].y + a.z * c[k].z + a.w * c[k].w;

    // Warp-reduce all 11 dot partials
    #pragma unroll
    for (int j = 0; j < K_NEG + 1; j++) {
        #pragma unroll
        for (int off = 16; off > 0; off >>= 1)
            dots[j] += __shfl_xor_sync(0xffffffffu, dots[j], off);
    }

    __shared__ float warp_sums[WARPS_PER_BLOCK];
    if (lane == 0) {
        float loss = log_sigmoid(dots[0]);
        #pragma unroll
        for (int k = 0; k < K_NEG; k++)
            loss += log_sigmoid(-dots[k + 1]);
        warp_sums[warp] = loss;
    }
    __syncthreads();

    // Deterministic in-block reduction (fixed order, done by thread 0)
    if (threadIdx.x == 0) {
        float bsum = 0.0f;
        #pragma unroll
        for (int w = 0; w < WARPS_PER_BLOCK; w++) bsum += warp_sums[w];
        g_partials[blockIdx.x] = bsum;
    }
}

// Single-block, fixed-order final reduction -> deterministic scalar
__global__ void __launch_bounds__(256)
skipgram_reduce_kernel(float* __restrict__ out)
{
    __shared__ double sh[256];
    const int tid = threadIdx.x;
    double acc = 0.0;
    // Fixed strided order per thread -> deterministic
    for (int i = tid; i < NBLOCKS; i += 256)
        acc += (double)g_partials[i];
    sh[tid] = acc;
    __syncthreads();
    // Fixed-order tree reduction
    for (int off = 128; off > 0; off >>= 1) {
        if (tid < off) sh[tid] += sh[tid + off];
        __syncthreads();
    }
    if (tid == 0)
        out[0] = (float)(sh[0] / (double)N_SAMPLES);
}

extern "C" void kernel_launch(void* const* d_in, const int* in_sizes, int n_in,
                              void* d_out, int out_size)
{
    const int*   input_idx  = (const int*)  d_in[0];
    const int*   output_idx = (const int*)  d_in[1];
    const int*   neg_idx    = (const int*)  d_in[2];
    const float* W_in       = (const float*)d_in[3];
    const float* W_out      = (const float*)d_in[4];
    float*       out        = (float*)d_out;

    skipgram_main_kernel<<<NBLOCKS, THREADS>>>(input_idx, output_idx, neg_idx, W_in, W_out);
    skipgram_reduce_kernel<<<1, 256>>>(out);
}